// round 1
// baseline (speedup 1.0000x reference)
#include <cuda_runtime.h>
#include <cuda_bf16.h>
#include <math.h>

// ---------------- scratch (no allocations allowed) ----------------
#define NQ 512
#define DM 1024
#define NEL (NQ * DM)

__device__ float g_txt[NEL];
__device__ float g_img[NEL];
__device__ float g_Q[2][NEL];
__device__ float g_K[2][NEL];
__device__ float g_V[2][NEL];
__device__ float g_O[2][NEL];

// ---------------- generic SGEMM: C = A(MxK) @ W(NxK)^T + bias (+ resid) ----
// BM=BN=64, BK=16, 256 threads, 4x4 per thread.
__global__ void sgemm_bias_kernel(const float* __restrict__ A,
                                  const float* __restrict__ W,
                                  const float* __restrict__ bias,
                                  const float* __restrict__ resid,
                                  float* __restrict__ C,
                                  int M, int N, int K) {
    __shared__ float As[16][65];
    __shared__ float Ws[16][65];
    const int tid = threadIdx.x;
    const int tx = tid & 15;        // 0..15 -> n
    const int ty = tid >> 4;        // 0..15 -> m
    const int m0 = blockIdx.y * 64;
    const int n0 = blockIdx.x * 64;

    float acc[4][4];
#pragma unroll
    for (int r = 0; r < 4; r++)
#pragma unroll
        for (int c = 0; c < 4; c++) acc[r][c] = 0.f;

    for (int k0 = 0; k0 < K; k0 += 16) {
#pragma unroll
        for (int it = 0; it < 4; it++) {
            int idx = tid + it * 256;          // 0..1023
            int k = idx & 15;
            int r = idx >> 4;                  // 0..63
            As[k][r] = A[(m0 + r) * K + (k0 + k)];
            Ws[k][r] = W[(n0 + r) * K + (k0 + k)];
        }
        __syncthreads();
#pragma unroll
        for (int kk = 0; kk < 16; kk++) {
            float a[4], b[4];
#pragma unroll
            for (int r = 0; r < 4; r++) a[r] = As[kk][ty + 16 * r];
#pragma unroll
            for (int c = 0; c < 4; c++) b[c] = Ws[kk][tx + 16 * c];
#pragma unroll
            for (int r = 0; r < 4; r++)
#pragma unroll
                for (int c = 0; c < 4; c++) acc[r][c] += a[r] * b[c];
        }
        __syncthreads();
    }

#pragma unroll
    for (int r = 0; r < 4; r++) {
        int m = m0 + ty + 16 * r;
#pragma unroll
        for (int c = 0; c < 4; c++) {
            int n = n0 + tx + 16 * c;
            float v = acc[r][c] + bias[n];
            if (resid) v += resid[m * N + n];
            C[m * N + n] = v;
        }
    }
}

// ---------------- sliding-window attention ----------------
// grid: (512, 2)   block: 256 (8 warps = 8 heads). One warp per (query, head).
// Valid slots p in [p_start, p_end), idx = i-32+p. Pads: n_pad slots with
// k=kb, v=vb, one shared score s_pad. Remaining invalid slots are masked.
__global__ void swattn_kernel(const float* __restrict__ kb0, const float* __restrict__ vb0,
                              const float* __restrict__ kb1, const float* __restrict__ vb1) {
    const int a = blockIdx.y;
    const int i = blockIdx.x;
    const int h = threadIdx.x >> 5;
    const int lane = threadIdx.x & 31;

    const float* __restrict__ Q  = g_Q[a];
    const float* __restrict__ Kc = g_K[a];
    const float* __restrict__ Vc = g_V[a];
    const float* __restrict__ kb = a ? kb1 : kb0;
    const float* __restrict__ vb = a ? vb1 : vb0;

    __shared__ float sc[8][66];

    const float scale = 0.08838834764831845f;  // 1/sqrt(128)
    const int base = h * 128 + lane * 4;
    const float4 q4 = *(const float4*)(Q + i * DM + base);

    const int lo = i - 32;
    const int p_start = max(0, 32 - i);
    const int p_end   = min(66, 544 - i);
    const int invalid = 66 - (p_end - p_start);
    const int n_pad   = max(0, invalid - 2);

    // scores for valid slots
    for (int p = p_start; p < p_end; p++) {
        const float4 k4 = *(const float4*)(Kc + (lo + p) * DM + base);
        float part = q4.x * k4.x + q4.y * k4.y + q4.z * k4.z + q4.w * k4.w;
#pragma unroll
        for (int off = 16; off > 0; off >>= 1)
            part += __shfl_xor_sync(0xffffffffu, part, off);
        if (lane == 0) sc[h][p] = part * scale;
    }

    // pad score
    float s_pad = -1e30f;
    if (n_pad > 0) {
        const float4 kb4 = *(const float4*)(kb + base);
        float part = q4.x * kb4.x + q4.y * kb4.y + q4.z * kb4.z + q4.w * kb4.w;
#pragma unroll
        for (int off = 16; off > 0; off >>= 1)
            part += __shfl_xor_sync(0xffffffffu, part, off);
        s_pad = part * scale;
    }
    __syncwarp();

    // max
    float mloc = (n_pad > 0) ? s_pad : -1e30f;
    for (int p = p_start + lane; p < p_end; p += 32) mloc = fmaxf(mloc, sc[h][p]);
#pragma unroll
    for (int off = 16; off > 0; off >>= 1)
        mloc = fmaxf(mloc, __shfl_xor_sync(0xffffffffu, mloc, off));
    const float m = mloc;

    // exp in place + denom
    float dloc = 0.f;
    for (int p = p_start + lane; p < p_end; p += 32) {
        float e = expf(sc[h][p] - m);
        sc[h][p] = e;
        dloc += e;
    }
#pragma unroll
    for (int off = 16; off > 0; off >>= 1)
        dloc += __shfl_xor_sync(0xffffffffu, dloc, off);
    float w_pad = 0.f;
    if (n_pad > 0) w_pad = (float)n_pad * expf(s_pad - m);
    const float denom = dloc + w_pad;
    __syncwarp();

    // weighted sum of V
    float4 acc = make_float4(0.f, 0.f, 0.f, 0.f);
    for (int p = p_start; p < p_end; p++) {
        const float w = sc[h][p];
        const float4 v4 = *(const float4*)(Vc + (lo + p) * DM + base);
        acc.x += w * v4.x; acc.y += w * v4.y; acc.z += w * v4.z; acc.w += w * v4.w;
    }
    if (n_pad > 0) {
        const float4 vb4 = *(const float4*)(vb + base);
        acc.x += w_pad * vb4.x; acc.y += w_pad * vb4.y;
        acc.z += w_pad * vb4.z; acc.w += w_pad * vb4.w;
    }
    const float inv = 1.f / denom;
    *(float4*)(g_O[a] + i * DM + base) =
        make_float4(acc.x * inv, acc.y * inv, acc.z * inv, acc.w * inv);
}

// ---------------- launcher ----------------
extern "C" void kernel_launch(void* const* d_in, const int* in_sizes, int n_in,
                              void* d_out, int out_size) {
    (void)in_sizes; (void)n_in; (void)out_size;

    const float* images   = (const float*)d_in[0];
    const float* captions = (const float*)d_in[1];
    // d_in[2] = text_input_ids (unused by reference math)
    const float* tp_w = (const float*)d_in[3];
    const float* tp_b = (const float*)d_in[4];
    const float* ip_w = (const float*)d_in[5];
    const float* ip_b = (const float*)d_in[6];
    // ia_: qw qb kw kb vw vb ow ob  (7..14), ta_: (15..22)
    const float* ia[8]; for (int k = 0; k < 8; k++) ia[k] = (const float*)d_in[7 + k];
    const float* ta[8]; for (int k = 0; k < 8; k++) ta[k] = (const float*)d_in[15 + k];
    float* out = (float*)d_out;

    float *txt, *img, *Qb, *Kb, *Vb, *Ob;
    cudaGetSymbolAddress((void**)&txt, g_txt);
    cudaGetSymbolAddress((void**)&img, g_img);
    cudaGetSymbolAddress((void**)&Qb, g_Q);
    cudaGetSymbolAddress((void**)&Kb, g_K);
    cudaGetSymbolAddress((void**)&Vb, g_V);
    cudaGetSymbolAddress((void**)&Ob, g_O);

    const dim3 gg(DM / 64, NQ / 64);   // (16, 8)
    const dim3 gb(256);

    // input projections
    sgemm_bias_kernel<<<gg, gb>>>(captions, tp_w, tp_b, nullptr, txt, NQ, DM, 768);
    sgemm_bias_kernel<<<gg, gb>>>(images,   ip_w, ip_b, nullptr, img, NQ, DM, 1024);

    // attention 0: queries=img, ctx=txt (ia_*); attention 1: queries=txt, ctx=img (ta_*)
    sgemm_bias_kernel<<<gg, gb>>>(img, ia[0], ia[1], nullptr, Qb + 0 * NEL, NQ, DM, DM);
    sgemm_bias_kernel<<<gg, gb>>>(txt, ia[2], ia[3], nullptr, Kb + 0 * NEL, NQ, DM, DM);
    sgemm_bias_kernel<<<gg, gb>>>(txt, ia[4], ia[5], nullptr, Vb + 0 * NEL, NQ, DM, DM);
    sgemm_bias_kernel<<<gg, gb>>>(txt, ta[0], ta[1], nullptr, Qb + 1 * NEL, NQ, DM, DM);
    sgemm_bias_kernel<<<gg, gb>>>(img, ta[2], ta[3], nullptr, Kb + 1 * NEL, NQ, DM, DM);
    sgemm_bias_kernel<<<gg, gb>>>(img, ta[4], ta[5], nullptr, Vb + 1 * NEL, NQ, DM, DM);

    // sliding-window attention (both modalities)
    swattn_kernel<<<dim3(NQ, 2), 256>>>(ia[3], ia[5], ta[3], ta[5]);

    // output projections + residual, straight into d_out (fused_img, fused_txt)
    sgemm_bias_kernel<<<gg, gb>>>(Ob + 0 * NEL, ia[6], ia[7], img, out,        NQ, DM, DM);
    sgemm_bias_kernel<<<gg, gb>>>(Ob + 1 * NEL, ta[6], ta[7], txt, out + NEL,  NQ, DM, DM);
}

// round 2
// speedup vs baseline: 5.5688x; 5.5688x over previous
#include <cuda_runtime.h>
#include <cuda_bf16.h>
#include <math.h>

#define NQ 512
#define DM 1024
#define NEL (NQ * DM)

__device__ float g_txt[NEL];
__device__ float g_img[NEL];
__device__ float g_Q[2][NEL];
__device__ float g_K[2][NEL];
__device__ float g_V[2][NEL];
__device__ float g_O[2][NEL];

// ---------------------------------------------------------------------------
// tf32 tensor-core GEMM:  C = A(512xK) @ W(1024xK)^T + bias (+ resid)
// BM=128, BN=64, BK=16, 256 threads (8 warps, 4Mx2N), warp tile 32x32.
// Batched over gridDim.z via GemmArgs (different A/W/bias/resid/C/K per set).
// ---------------------------------------------------------------------------
struct GemmArgs {
    const float* A[6];
    const float* W[6];
    const float* bias[6];
    const float* resid[6];
    float*       C[6];
    int          K[6];
};

__device__ __forceinline__ unsigned f2tf32(float x) {
    unsigned u;
    asm("cvt.rna.tf32.f32 %0, %1;" : "=r"(u) : "f"(x));
    return u;
}

__global__ __launch_bounds__(256) void gemm_tf32_kernel(GemmArgs args) {
    const int z = blockIdx.z;
    const float* __restrict__ A     = args.A[z];
    const float* __restrict__ W     = args.W[z];
    const float* __restrict__ bias  = args.bias[z];
    const float* __restrict__ resid = args.resid[z];
    float* __restrict__ C           = args.C[z];
    const int K = args.K[z];

    const int m0 = blockIdx.y * 128;
    const int n0 = blockIdx.x * 64;

    __shared__ unsigned As[128][20];   // [row][k], pad to 20 (conflict-free)
    __shared__ unsigned Ws[64][20];    // [n][k]

    const int tid  = threadIdx.x;
    const int lane = tid & 31;
    const int wid  = tid >> 5;
    const int wm   = (wid & 3) * 32;   // warp M offset within tile
    const int wn   = (wid >> 2) * 32;  // warp N offset within tile
    const int g    = lane >> 2;        // groupID 0..7
    const int tg   = lane & 3;         // thread-in-group 0..3

    float acc[2][4][4];
#pragma unroll
    for (int mt = 0; mt < 2; mt++)
#pragma unroll
        for (int nt = 0; nt < 4; nt++)
#pragma unroll
            for (int r = 0; r < 4; r++) acc[mt][nt][r] = 0.f;

    for (int k0 = 0; k0 < K; k0 += 16) {
        // ---- load A tile (128x16): 2 float4 per thread ----
#pragma unroll
        for (int it = 0; it < 2; it++) {
            int f  = tid + it * 256;       // 0..511
            int r  = f >> 2;               // row 0..127
            int kq = f & 3;                // float4 within row
            float4 v = *(const float4*)(A + (m0 + r) * K + k0 + kq * 4);
            uint4 u = make_uint4(f2tf32(v.x), f2tf32(v.y), f2tf32(v.z), f2tf32(v.w));
            *(uint4*)(&As[r][kq * 4]) = u;
        }
        // ---- load W tile (64x16): 1 float4 per thread ----
        {
            int r  = tid >> 2;             // n 0..63
            int kq = tid & 3;
            float4 v = *(const float4*)(W + (n0 + r) * K + k0 + kq * 4);
            uint4 u = make_uint4(f2tf32(v.x), f2tf32(v.y), f2tf32(v.z), f2tf32(v.w));
            *(uint4*)(&Ws[r][kq * 4]) = u;
        }
        __syncthreads();

#pragma unroll
        for (int ks = 0; ks < 2; ks++) {
            const int kb = ks * 8;
            unsigned a[2][4], b[4][2];
#pragma unroll
            for (int mt = 0; mt < 2; mt++) {
                int row = wm + mt * 16 + g;
                a[mt][0] = As[row][kb + tg];
                a[mt][1] = As[row + 8][kb + tg];
                a[mt][2] = As[row][kb + tg + 4];
                a[mt][3] = As[row + 8][kb + tg + 4];
            }
#pragma unroll
            for (int nt = 0; nt < 4; nt++) {
                int n = wn + nt * 8 + g;
                b[nt][0] = Ws[n][kb + tg];
                b[nt][1] = Ws[n][kb + tg + 4];
            }
#pragma unroll
            for (int mt = 0; mt < 2; mt++)
#pragma unroll
                for (int nt = 0; nt < 4; nt++) {
                    asm volatile(
                        "mma.sync.aligned.m16n8k8.row.col.f32.tf32.tf32.f32 "
                        "{%0,%1,%2,%3}, {%4,%5,%6,%7}, {%8,%9}, {%0,%1,%2,%3};"
                        : "+f"(acc[mt][nt][0]), "+f"(acc[mt][nt][1]),
                          "+f"(acc[mt][nt][2]), "+f"(acc[mt][nt][3])
                        : "r"(a[mt][0]), "r"(a[mt][1]), "r"(a[mt][2]), "r"(a[mt][3]),
                          "r"(b[nt][0]), "r"(b[nt][1]));
                }
        }
        __syncthreads();
    }

    // ---- epilogue: bias (+resid), float2 stores ----
#pragma unroll
    for (int mt = 0; mt < 2; mt++) {
#pragma unroll
        for (int nt = 0; nt < 4; nt++) {
            int row0 = m0 + wm + mt * 16 + g;
            int col  = n0 + wn + nt * 8 + tg * 2;
            float b0 = bias[col], b1 = bias[col + 1];
            float2 v0 = make_float2(acc[mt][nt][0] + b0, acc[mt][nt][1] + b1);
            float2 v1 = make_float2(acc[mt][nt][2] + b0, acc[mt][nt][3] + b1);
            if (resid) {
                float2 r0 = *(const float2*)(resid + row0 * DM + col);
                float2 r1 = *(const float2*)(resid + (row0 + 8) * DM + col);
                v0.x += r0.x; v0.y += r0.y;
                v1.x += r1.x; v1.y += r1.y;
            }
            *(float2*)(C + row0 * DM + col)       = v0;
            *(float2*)(C + (row0 + 8) * DM + col) = v1;
        }
    }
}

// ---------------------------------------------------------------------------
// sliding-window attention: one warp per (query, head)
// ---------------------------------------------------------------------------
__global__ void swattn_kernel(const float* __restrict__ kb0, const float* __restrict__ vb0,
                              const float* __restrict__ kb1, const float* __restrict__ vb1) {
    const int a = blockIdx.y;
    const int i = blockIdx.x;
    const int h = threadIdx.x >> 5;
    const int lane = threadIdx.x & 31;

    const float* __restrict__ Q  = g_Q[a];
    const float* __restrict__ Kc = g_K[a];
    const float* __restrict__ Vc = g_V[a];
    const float* __restrict__ kb = a ? kb1 : kb0;
    const float* __restrict__ vb = a ? vb1 : vb0;

    __shared__ float sc[8][66];

    const float scale = 0.08838834764831845f;  // 1/sqrt(128)
    const int base = h * 128 + lane * 4;
    const float4 q4 = *(const float4*)(Q + i * DM + base);

    const int lo = i - 32;
    const int p_start = max(0, 32 - i);
    const int p_end   = min(66, 544 - i);
    const int invalid = 66 - (p_end - p_start);
    const int n_pad   = max(0, invalid - 2);

    for (int p = p_start; p < p_end; p++) {
        const float4 k4 = *(const float4*)(Kc + (lo + p) * DM + base);
        float part = q4.x * k4.x + q4.y * k4.y + q4.z * k4.z + q4.w * k4.w;
#pragma unroll
        for (int off = 16; off > 0; off >>= 1)
            part += __shfl_xor_sync(0xffffffffu, part, off);
        if (lane == 0) sc[h][p] = part * scale;
    }

    float s_pad = -1e30f;
    if (n_pad > 0) {
        const float4 kb4 = *(const float4*)(kb + base);
        float part = q4.x * kb4.x + q4.y * kb4.y + q4.z * kb4.z + q4.w * kb4.w;
#pragma unroll
        for (int off = 16; off > 0; off >>= 1)
            part += __shfl_xor_sync(0xffffffffu, part, off);
        s_pad = part * scale;
    }
    __syncwarp();

    float mloc = (n_pad > 0) ? s_pad : -1e30f;
    for (int p = p_start + lane; p < p_end; p += 32) mloc = fmaxf(mloc, sc[h][p]);
#pragma unroll
    for (int off = 16; off > 0; off >>= 1)
        mloc = fmaxf(mloc, __shfl_xor_sync(0xffffffffu, mloc, off));
    const float m = mloc;

    float dloc = 0.f;
    for (int p = p_start + lane; p < p_end; p += 32) {
        float e = expf(sc[h][p] - m);
        sc[h][p] = e;
        dloc += e;
    }
#pragma unroll
    for (int off = 16; off > 0; off >>= 1)
        dloc += __shfl_xor_sync(0xffffffffu, dloc, off);
    float w_pad = 0.f;
    if (n_pad > 0) w_pad = (float)n_pad * expf(s_pad - m);
    const float denom = dloc + w_pad;
    __syncwarp();

    float4 acc = make_float4(0.f, 0.f, 0.f, 0.f);
    for (int p = p_start; p < p_end; p++) {
        const float w = sc[h][p];
        const float4 v4 = *(const float4*)(Vc + (lo + p) * DM + base);
        acc.x += w * v4.x; acc.y += w * v4.y; acc.z += w * v4.z; acc.w += w * v4.w;
    }
    if (n_pad > 0) {
        const float4 vb4 = *(const float4*)(vb + base);
        acc.x += w_pad * vb4.x; acc.y += w_pad * vb4.y;
        acc.z += w_pad * vb4.z; acc.w += w_pad * vb4.w;
    }
    const float inv = 1.f / denom;
    *(float4*)(g_O[a] + i * DM + base) =
        make_float4(acc.x * inv, acc.y * inv, acc.z * inv, acc.w * inv);
}

// ---------------------------------------------------------------------------
extern "C" void kernel_launch(void* const* d_in, const int* in_sizes, int n_in,
                              void* d_out, int out_size) {
    (void)in_sizes; (void)n_in; (void)out_size;

    const float* images   = (const float*)d_in[0];
    const float* captions = (const float*)d_in[1];
    const float* tp_w = (const float*)d_in[3];
    const float* tp_b = (const float*)d_in[4];
    const float* ip_w = (const float*)d_in[5];
    const float* ip_b = (const float*)d_in[6];
    const float* ia[8]; for (int k = 0; k < 8; k++) ia[k] = (const float*)d_in[7 + k];
    const float* ta[8]; for (int k = 0; k < 8; k++) ta[k] = (const float*)d_in[15 + k];
    float* out = (float*)d_out;

    float *txt, *img, *Qb, *Kb, *Vb, *Ob;
    cudaGetSymbolAddress((void**)&txt, g_txt);
    cudaGetSymbolAddress((void**)&img, g_img);
    cudaGetSymbolAddress((void**)&Qb, g_Q);
    cudaGetSymbolAddress((void**)&Kb, g_K);
    cudaGetSymbolAddress((void**)&Vb, g_V);
    cudaGetSymbolAddress((void**)&Ob, g_O);

    const dim3 blk(256);
    const int GX = DM / 64;   // 16
    const int GY = NQ / 128;  // 4

    // ---- launch 1: both input projections (z=2) ----
    {
        GemmArgs ar{};
        ar.A[0] = captions; ar.W[0] = tp_w; ar.bias[0] = tp_b; ar.resid[0] = nullptr; ar.C[0] = txt; ar.K[0] = 768;
        ar.A[1] = images;   ar.W[1] = ip_w; ar.bias[1] = ip_b; ar.resid[1] = nullptr; ar.C[1] = img; ar.K[1] = 1024;
        gemm_tf32_kernel<<<dim3(GX, GY, 2), blk>>>(ar);
    }

    // ---- launch 2: all six QKV projections (z=6) ----
    {
        GemmArgs ar{};
        const float* Aarr[6]  = { img,  txt,  txt,  txt,  img,  img  };
        const float* Warr[6]  = { ia[0], ia[2], ia[4], ta[0], ta[2], ta[4] };
        const float* Barr[6]  = { ia[1], ia[3], ia[5], ta[1], ta[3], ta[5] };
        float*       Carr[6]  = { Qb, Kb, Vb, Qb + NEL, Kb + NEL, Vb + NEL };
        for (int s = 0; s < 6; s++) {
            ar.A[s] = Aarr[s]; ar.W[s] = Warr[s]; ar.bias[s] = Barr[s];
            ar.resid[s] = nullptr; ar.C[s] = Carr[s]; ar.K[s] = 1024;
        }
        gemm_tf32_kernel<<<dim3(GX, GY, 6), blk>>>(ar);
    }

    // ---- launch 3: sliding-window attention ----
    swattn_kernel<<<dim3(NQ, 2), 256>>>(ia[3], ia[5], ta[3], ta[5]);

    // ---- launch 4: both output projections + residual (z=2) ----
    {
        GemmArgs ar{};
        ar.A[0] = Ob;       ar.W[0] = ia[6]; ar.bias[0] = ia[7]; ar.resid[0] = img; ar.C[0] = out;       ar.K[0] = 1024;
        ar.A[1] = Ob + NEL; ar.W[1] = ta[6]; ar.bias[1] = ta[7]; ar.resid[1] = txt; ar.C[1] = out + NEL; ar.K[1] = 1024;
        gemm_tf32_kernel<<<dim3(GX, GY, 2), blk>>>(ar);
    }
}

// round 3
// speedup vs baseline: 7.6442x; 1.3727x over previous
#include <cuda_runtime.h>
#include <cuda_bf16.h>
#include <math.h>

#define NQ 512
#define DM 1024
#define NEL (NQ * DM)

__device__ float g_txt[NEL];
__device__ float g_img[NEL];
__device__ float g_Q[2][NEL];
__device__ float g_K[2][NEL];
__device__ float g_V[2][NEL];
__device__ float g_O[2][NEL];

// ---------------------------------------------------------------------------
// tf32 tensor-core GEMM:  C = A(512xK) @ W(1024xK)^T + bias (+ resid)
// BM=128, BN=64, BK=32, 256 threads (8 warps, 4Mx2N), warp tile 32x32.
// Software pipeline: prefetch next K-tile into registers during MMA.
// ---------------------------------------------------------------------------
struct GemmArgs {
    const float* A[6];
    const float* W[6];
    const float* bias[6];
    const float* resid[6];
    float*       C[6];
    int          K[6];
};

__device__ __forceinline__ unsigned f2tf32(float x) {
    unsigned u;
    asm("cvt.rna.tf32.f32 %0, %1;" : "=r"(u) : "f"(x));
    return u;
}
__device__ __forceinline__ uint4 cvt4(float4 v) {
    return make_uint4(f2tf32(v.x), f2tf32(v.y), f2tf32(v.z), f2tf32(v.w));
}

__global__ __launch_bounds__(256) void gemm_tf32_kernel(GemmArgs args) {
    const int z = blockIdx.z;
    const float* __restrict__ A     = args.A[z];
    const float* __restrict__ W     = args.W[z];
    const float* __restrict__ bias  = args.bias[z];
    const float* __restrict__ resid = args.resid[z];
    float* __restrict__ C           = args.C[z];
    const int K = args.K[z];

    const int m0 = blockIdx.y * 128;
    const int n0 = blockIdx.x * 64;

    // row stride 36 words: fragment LDS bank = (4g+tg) -> all 32 distinct
    __shared__ unsigned As[128][36];
    __shared__ unsigned Ws[64][36];

    const int tid  = threadIdx.x;
    const int lane = tid & 31;
    const int wid  = tid >> 5;
    const int wm   = (wid & 3) * 32;   // warp M offset
    const int wn   = (wid >> 2) * 32;  // warp N offset
    const int g    = lane >> 2;        // 0..7
    const int tg   = lane & 3;         // 0..3

    // per-thread load mapping (BK=32: 8 float4 per row)
    const int arow = tid >> 3;         // A: rows tid/8 (+32 per it), 0..127
    const int aq   = tid & 7;          // float4 index within row
    const int wrow = tid >> 3;         // W: rows 0..31 (+32 for it=1)
    const int wq   = tid & 7;

    float acc[2][4][4];
#pragma unroll
    for (int mt = 0; mt < 2; mt++)
#pragma unroll
        for (int nt = 0; nt < 4; nt++)
#pragma unroll
            for (int r = 0; r < 4; r++) acc[mt][nt][r] = 0.f;

    float4 pa[4], pw[2];
    const int T = K >> 5;

    // prologue: load tile 0
#pragma unroll
    for (int it = 0; it < 4; it++)
        pa[it] = *(const float4*)(A + (m0 + arow + it * 32) * K + aq * 4);
#pragma unroll
    for (int it = 0; it < 2; it++)
        pw[it] = *(const float4*)(W + (n0 + wrow + it * 32) * K + wq * 4);

    for (int t = 0; t < T; t++) {
        // store current tile to smem (cvt to tf32)
#pragma unroll
        for (int it = 0; it < 4; it++)
            *(uint4*)(&As[arow + it * 32][aq * 4]) = cvt4(pa[it]);
#pragma unroll
        for (int it = 0; it < 2; it++)
            *(uint4*)(&Ws[wrow + it * 32][wq * 4]) = cvt4(pw[it]);
        __syncthreads();

        // prefetch next tile (LDG issues overlap the MMA section below)
        if (t + 1 < T) {
            const int k0 = (t + 1) * 32;
#pragma unroll
            for (int it = 0; it < 4; it++)
                pa[it] = *(const float4*)(A + (m0 + arow + it * 32) * K + k0 + aq * 4);
#pragma unroll
            for (int it = 0; it < 2; it++)
                pw[it] = *(const float4*)(W + (n0 + wrow + it * 32) * K + k0 + wq * 4);
        }

        // MMA over 4 k8-steps
#pragma unroll
        for (int ks = 0; ks < 4; ks++) {
            const int kb = ks * 8;
            unsigned a[2][4], b[4][2];
#pragma unroll
            for (int mt = 0; mt < 2; mt++) {
                int row = wm + mt * 16 + g;
                a[mt][0] = As[row][kb + tg];
                a[mt][1] = As[row + 8][kb + tg];
                a[mt][2] = As[row][kb + tg + 4];
                a[mt][3] = As[row + 8][kb + tg + 4];
            }
#pragma unroll
            for (int nt = 0; nt < 4; nt++) {
                int n = wn + nt * 8 + g;
                b[nt][0] = Ws[n][kb + tg];
                b[nt][1] = Ws[n][kb + tg + 4];
            }
#pragma unroll
            for (int mt = 0; mt < 2; mt++)
#pragma unroll
                for (int nt = 0; nt < 4; nt++) {
                    asm volatile(
                        "mma.sync.aligned.m16n8k8.row.col.f32.tf32.tf32.f32 "
                        "{%0,%1,%2,%3}, {%4,%5,%6,%7}, {%8,%9}, {%0,%1,%2,%3};"
                        : "+f"(acc[mt][nt][0]), "+f"(acc[mt][nt][1]),
                          "+f"(acc[mt][nt][2]), "+f"(acc[mt][nt][3])
                        : "r"(a[mt][0]), "r"(a[mt][1]), "r"(a[mt][2]), "r"(a[mt][3]),
                          "r"(b[nt][0]), "r"(b[nt][1]));
                }
        }
        __syncthreads();
    }

    // epilogue: bias (+resid)
#pragma unroll
    for (int mt = 0; mt < 2; mt++) {
#pragma unroll
        for (int nt = 0; nt < 4; nt++) {
            int row0 = m0 + wm + mt * 16 + g;
            int col  = n0 + wn + nt * 8 + tg * 2;
            float b0 = bias[col], b1 = bias[col + 1];
            float2 v0 = make_float2(acc[mt][nt][0] + b0, acc[mt][nt][1] + b1);
            float2 v1 = make_float2(acc[mt][nt][2] + b0, acc[mt][nt][3] + b1);
            if (resid) {
                float2 r0 = *(const float2*)(resid + row0 * DM + col);
                float2 r1 = *(const float2*)(resid + (row0 + 8) * DM + col);
                v0.x += r0.x; v0.y += r0.y;
                v1.x += r1.x; v1.y += r1.y;
            }
            *(float2*)(C + row0 * DM + col)       = v0;
            *(float2*)(C + (row0 + 8) * DM + col) = v1;
        }
    }
}

// ---------------------------------------------------------------------------
// sliding-window attention: one warp per (query, head)
// ---------------------------------------------------------------------------
__global__ void swattn_kernel(const float* __restrict__ kb0, const float* __restrict__ vb0,
                              const float* __restrict__ kb1, const float* __restrict__ vb1) {
    const int a = blockIdx.y;
    const int i = blockIdx.x;
    const int h = threadIdx.x >> 5;
    const int lane = threadIdx.x & 31;

    const float* __restrict__ Q  = g_Q[a];
    const float* __restrict__ Kc = g_K[a];
    const float* __restrict__ Vc = g_V[a];
    const float* __restrict__ kb = a ? kb1 : kb0;
    const float* __restrict__ vb = a ? vb1 : vb0;

    __shared__ float sc[8][66];

    const float scale = 0.08838834764831845f;  // 1/sqrt(128)
    const int base = h * 128 + lane * 4;
    const float4 q4 = *(const float4*)(Q + i * DM + base);

    const int lo = i - 32;
    const int p_start = max(0, 32 - i);
    const int p_end   = min(66, 544 - i);
    const int invalid = 66 - (p_end - p_start);
    const int n_pad   = max(0, invalid - 2);

    for (int p = p_start; p < p_end; p++) {
        const float4 k4 = *(const float4*)(Kc + (lo + p) * DM + base);
        float part = q4.x * k4.x + q4.y * k4.y + q4.z * k4.z + q4.w * k4.w;
#pragma unroll
        for (int off = 16; off > 0; off >>= 1)
            part += __shfl_xor_sync(0xffffffffu, part, off);
        if (lane == 0) sc[h][p] = part * scale;
    }

    float s_pad = -1e30f;
    if (n_pad > 0) {
        const float4 kb4 = *(const float4*)(kb + base);
        float part = q4.x * kb4.x + q4.y * kb4.y + q4.z * kb4.z + q4.w * kb4.w;
#pragma unroll
        for (int off = 16; off > 0; off >>= 1)
            part += __shfl_xor_sync(0xffffffffu, part, off);
        s_pad = part * scale;
    }
    __syncwarp();

    float mloc = (n_pad > 0) ? s_pad : -1e30f;
    for (int p = p_start + lane; p < p_end; p += 32) mloc = fmaxf(mloc, sc[h][p]);
#pragma unroll
    for (int off = 16; off > 0; off >>= 1)
        mloc = fmaxf(mloc, __shfl_xor_sync(0xffffffffu, mloc, off));
    const float m = mloc;

    float dloc = 0.f;
    for (int p = p_start + lane; p < p_end; p += 32) {
        float e = expf(sc[h][p] - m);
        sc[h][p] = e;
        dloc += e;
    }
#pragma unroll
    for (int off = 16; off > 0; off >>= 1)
        dloc += __shfl_xor_sync(0xffffffffu, dloc, off);
    float w_pad = 0.f;
    if (n_pad > 0) w_pad = (float)n_pad * expf(s_pad - m);
    const float denom = dloc + w_pad;
    __syncwarp();

    float4 acc = make_float4(0.f, 0.f, 0.f, 0.f);
    for (int p = p_start; p < p_end; p++) {
        const float w = sc[h][p];
        const float4 v4 = *(const float4*)(Vc + (lo + p) * DM + base);
        acc.x += w * v4.x; acc.y += w * v4.y; acc.z += w * v4.z; acc.w += w * v4.w;
    }
    if (n_pad > 0) {
        const float4 vb4 = *(const float4*)(vb + base);
        acc.x += w_pad * vb4.x; acc.y += w_pad * vb4.y;
        acc.z += w_pad * vb4.z; acc.w += w_pad * vb4.w;
    }
    const float inv = 1.f / denom;
    *(float4*)(g_O[a] + i * DM + base) =
        make_float4(acc.x * inv, acc.y * inv, acc.z * inv, acc.w * inv);
}

// ---------------------------------------------------------------------------
extern "C" void kernel_launch(void* const* d_in, const int* in_sizes, int n_in,
                              void* d_out, int out_size) {
    (void)in_sizes; (void)n_in; (void)out_size;

    const float* images   = (const float*)d_in[0];
    const float* captions = (const float*)d_in[1];
    const float* tp_w = (const float*)d_in[3];
    const float* tp_b = (const float*)d_in[4];
    const float* ip_w = (const float*)d_in[5];
    const float* ip_b = (const float*)d_in[6];
    const float* ia[8]; for (int k = 0; k < 8; k++) ia[k] = (const float*)d_in[7 + k];
    const float* ta[8]; for (int k = 0; k < 8; k++) ta[k] = (const float*)d_in[15 + k];
    float* out = (float*)d_out;

    float *txt, *img, *Qb, *Kb, *Vb, *Ob;
    cudaGetSymbolAddress((void**)&txt, g_txt);
    cudaGetSymbolAddress((void**)&img, g_img);
    cudaGetSymbolAddress((void**)&Qb, g_Q);
    cudaGetSymbolAddress((void**)&Kb, g_K);
    cudaGetSymbolAddress((void**)&Vb, g_V);
    cudaGetSymbolAddress((void**)&Ob, g_O);

    const dim3 blk(256);
    const int GX = DM / 64;   // 16
    const int GY = NQ / 128;  // 4

    // ---- launch 1: both input projections (z=2) ----
    {
        GemmArgs ar{};
        ar.A[0] = captions; ar.W[0] = tp_w; ar.bias[0] = tp_b; ar.resid[0] = nullptr; ar.C[0] = txt; ar.K[0] = 768;
        ar.A[1] = images;   ar.W[1] = ip_w; ar.bias[1] = ip_b; ar.resid[1] = nullptr; ar.C[1] = img; ar.K[1] = 1024;
        gemm_tf32_kernel<<<dim3(GX, GY, 2), blk>>>(ar);
    }

    // ---- launch 2: all six QKV projections (z=6) ----
    {
        GemmArgs ar{};
        const float* Aarr[6]  = { img,  txt,  txt,  txt,  img,  img  };
        const float* Warr[6]  = { ia[0], ia[2], ia[4], ta[0], ta[2], ta[4] };
        const float* Barr[6]  = { ia[1], ia[3], ia[5], ta[1], ta[3], ta[5] };
        float*       Carr[6]  = { Qb, Kb, Vb, Qb + NEL, Kb + NEL, Vb + NEL };
        for (int s = 0; s < 6; s++) {
            ar.A[s] = Aarr[s]; ar.W[s] = Warr[s]; ar.bias[s] = Barr[s];
            ar.resid[s] = nullptr; ar.C[s] = Carr[s]; ar.K[s] = 1024;
        }
        gemm_tf32_kernel<<<dim3(GX, GY, 6), blk>>>(ar);
    }

    // ---- launch 3: sliding-window attention ----
    swattn_kernel<<<dim3(NQ, 2), 256>>>(ia[3], ia[5], ta[3], ta[5]);

    // ---- launch 4: both output projections + residual (z=2) ----
    {
        GemmArgs ar{};
        ar.A[0] = Ob;       ar.W[0] = ia[6]; ar.bias[0] = ia[7]; ar.resid[0] = img; ar.C[0] = out;       ar.K[0] = 1024;
        ar.A[1] = Ob + NEL; ar.W[1] = ta[6]; ar.bias[1] = ta[7]; ar.resid[1] = txt; ar.C[1] = out + NEL; ar.K[1] = 1024;
        gemm_tf32_kernel<<<dim3(GX, GY, 2), blk>>>(ar);
    }
}